// round 16
// baseline (speedup 1.0000x reference)
#include <cuda_runtime.h>

// Net0: x[B,2] -> fc1(2,7)+ELU -> 19x fc(7,7)+ELU -> fc(7,2) -> log_softmax.
// R16 = R13 (best: 260us, i-major ping-pong) + two scheduling changes:
//  (1) UNIQUE weight vregs per step (no WAR chains) -> ptxas can hoist/pipeline
//      the 28 LDS of a layer into earlier steps' FMA/MUFU shadows.
//  (2) ex2-FIRST ELU: e = ex2(t); min(e,1); max(t,0); ffma  (identical math:
//      t>0 => exp2 in (1,inf], min clamps to 1; t<=0 branch unchanged).
// Algebra (validated R9-R15): state t = z*log2e; G = log2e*(elu(z)+1);
//   mid weights RAW; bias' = (b - rowsum(W))*log2e; fc21 uses ln2*Wo.

constexpr int H       = 7;
constexpr int NMID    = 19;
constexpr int THREADS = 256;

typedef unsigned long long u64;

__device__ __forceinline__ u64 pack2(float lo, float hi) {
    u64 r; asm("mov.b64 %0, {%1, %2};" : "=l"(r) : "f"(lo), "f"(hi)); return r;
}
__device__ __forceinline__ void unpack2(u64 v, float& lo, float& hi) {
    asm("mov.b64 {%0, %1}, %2;" : "=f"(lo), "=f"(hi) : "l"(v));
}
__device__ __forceinline__ u64 fma2(u64 a, u64 b, u64 c) {
    u64 d; asm("fma.rn.f32x2 %0, %1, %2, %3;" : "=l"(d) : "l"(a), "l"(b), "l"(c));
    return d;
}
__device__ __forceinline__ float ex2f(float x) {
    float r; asm("ex2.approx.f32 %0, %1;" : "=f"(r) : "f"(x)); return r;
}
__device__ __forceinline__ float eluG1(float t) {   // scalar, fc1 only
    return fmaf(1.44269504088896340736f, fminf(ex2f(t), 1.0f), fmaxf(t, 0.0f));
}

// ---- PTX text macros ----
// ex2-first ELU: e=2^t; G = log2e*min(e,1) + max(t,0). Unique regs/instance.
#define ELUS(ACC,G,E0,E1,M0,M1) \
  "mov.b64 {" E0 "," E1 "}, " ACC ";\n\t" \
  "ex2.approx.f32 " M0 "," E0 ";\n\t" \
  "ex2.approx.f32 " M1 "," E1 ";\n\t" \
  "min.f32 " M0 "," M0 ", 0f3F800000;\n\t" \
  "min.f32 " M1 "," M1 ", 0f3F800000;\n\t" \
  "max.f32 " E0 "," E0 ", 0f00000000;\n\t" \
  "max.f32 " E1 "," E1 ", 0f00000000;\n\t" \
  "fma.rn.f32 " E0 "," M0 ", 0f3FB8AA3B," E0 ";\n\t" \
  "fma.rn.f32 " E1 "," M1 ", 0f3FB8AA3B," E1 ";\n\t" \
  "mov.b64 " G ", {" E0 "," E1 "};\n\t"

// One i-step with its OWN weight regs W0..W7 (W is a string prefix; W "0"
// string-concatenates). 4x LDS.128 (7 weights + bias), 14 fma2, 2 ELUs.
#define STEP_(O0,O1,O2,O3, W, I0,I1,I2,I3,I4,I5,I6, J0,J1,J2,J3,J4,J5,J6, \
              NA,NB,GA,GB, EA0,EA1,MA0,MA1, EB0,EB1,MB0,MB1) \
  "ld.shared.v2.b64 {" W "0," W "1},[%14+" O0 "];\n\t" \
  "ld.shared.v2.b64 {" W "2," W "3},[%14+" O1 "];\n\t" \
  "ld.shared.v2.b64 {" W "4," W "5},[%14+" O2 "];\n\t" \
  "ld.shared.v2.b64 {" W "6," W "7},[%14+" O3 "];\n\t" \
  "fma.rn.f32x2 " NA "," W "0," I0 "," W "7;\n\t" \
  "fma.rn.f32x2 " NB "," W "0," J0 "," W "7;\n\t" \
  "fma.rn.f32x2 " NA "," W "1," I1 "," NA ";\n\t" \
  "fma.rn.f32x2 " NB "," W "1," J1 "," NB ";\n\t" \
  "fma.rn.f32x2 " NA "," W "2," I2 "," NA ";\n\t" \
  "fma.rn.f32x2 " NB "," W "2," J2 "," NB ";\n\t" \
  "fma.rn.f32x2 " NA "," W "3," I3 "," NA ";\n\t" \
  "fma.rn.f32x2 " NB "," W "3," J3 "," NB ";\n\t" \
  "fma.rn.f32x2 " NA "," W "4," I4 "," NA ";\n\t" \
  "fma.rn.f32x2 " NB "," W "4," J4 "," NB ";\n\t" \
  "fma.rn.f32x2 " NA "," W "5," I5 "," NA ";\n\t" \
  "fma.rn.f32x2 " NB "," W "5," J5 "," NB ";\n\t" \
  "fma.rn.f32x2 " NA "," W "6," I6 "," NA ";\n\t" \
  "fma.rn.f32x2 " NB "," W "6," J6 "," NB ";\n\t" \
  ELUS(NA,GA,EA0,EA1,MA0,MA1) \
  ELUS(NB,GB,EB0,EB1,MB0,MB1)

// Variadic trampoline: forces INA/INB to expand BEFORE argument counting.
#define STEP(...) STEP_(__VA_ARGS__)

#define INA "%0","%1","%2","%3","%4","%5","%6"
#define INB "%7","%8","%9","%10","%11","%12","%13"
#define GAS "gA0","gA1","gA2","gA3","gA4","gA5","gA6"
#define GBS "gB0","gB1","gB2","gB3","gB4","gB5","gB6"

__global__ void __launch_bounds__(THREADS, 3)
net0_kernel(const float* __restrict__ x,
            const float* __restrict__ W1, const float* __restrict__ b1,
            const float* __restrict__ Wm, const float* __restrict__ bm,
            const float* __restrict__ Wo, const float* __restrict__ bo,
            float* __restrict__ out, int nQuads)
{
    __shared__ __align__(16) float2 sFc1[H * 4];        // {w0d,w1d,bd,pad} x log2e
    __shared__ __align__(16) float2 sMid[NMID * 64];    // i-major rows: 7w dup + bias' dup
    __shared__ __align__(16) float2 sFcO[2 * 8];        // (ln2*Wo)d + bias-fold d

    const float LOG2E = 1.44269504088896340736f;
    const float LN2   = 0.69314718055994530942f;

    for (int idx = threadIdx.x; idx < H * 4; idx += THREADS) {
        int i = idx >> 2, k = idx & 3;
        float v = (k < 2) ? W1[i * 2 + k] * LOG2E
                          : (k == 2 ? b1[i] * LOG2E : 0.0f);
        sFc1[idx] = make_float2(v, v);
    }
    // per layer: row i (i<7): slots k<7 = RAW Wm[l][i][k], k=7 = (b - rowsum)*log2e.
    for (int idx = threadIdx.x; idx < NMID * 64; idx += THREADS) {
        int l = idx >> 6;
        int r = idx & 63;
        int i = r >> 3, k = r & 7;
        float v = 0.0f;
        if (i < 7) {
            if (k < 7) {
                v = Wm[(l * H + i) * H + k];
            } else {
                float s = 0.0f;
                for (int j = 0; j < H; j++) s += Wm[(l * H + i) * H + j];
                v = (bm[l * H + i] - s) * LOG2E;
            }
        }
        sMid[idx] = make_float2(v, v);
    }
    for (int idx = threadIdx.x; idx < 16; idx += THREADS) {
        int r = idx >> 3, k = idx & 7;
        float v;
        if (k < 7) {
            v = Wo[r * H + k] * LN2;
        } else {
            float s = 0.0f;
            for (int j = 0; j < H; j++) s += Wo[r * H + j];
            v = bo[r] - s;
        }
        sFcO[idx] = make_float2(v, v);
    }
    __syncthreads();

    // Volatile producer of sbase AFTER the barrier: pins all dependent
    // (non-volatile) layer blocks after __syncthreads.
    unsigned sbase;
    {
        unsigned long long gen = (unsigned long long)__cvta_generic_to_shared(sMid);
        asm volatile("cvt.u32.u64 %0, %1;" : "=r"(sbase) : "l"(gen));
    }

    int q = blockIdx.x * THREADS + threadIdx.x;   // 4 rows per thread
    if (q >= nQuads) return;

    float4 xa = reinterpret_cast<const float4*>(x)[2 * q + 0];
    float4 xb = reinterpret_cast<const float4*>(x)[2 * q + 1];

    // ---- fc1 (t-scale) + ELU(G), scalar ----
    float g[4][H];
#pragma unroll
    for (int i = 0; i < H; i++) {
        float w0 = sFc1[i * 4 + 0].x;
        float w1 = sFc1[i * 4 + 1].x;
        float bb = sFc1[i * 4 + 2].x;
        g[0][i] = eluG1(fmaf(w0, xa.x, fmaf(w1, xa.y, bb)));
        g[1][i] = eluG1(fmaf(w0, xa.z, fmaf(w1, xa.w, bb)));
        g[2][i] = eluG1(fmaf(w0, xb.x, fmaf(w1, xb.y, bb)));
        g[3][i] = eluG1(fmaf(w0, xb.z, fmaf(w1, xb.w, bb)));
    }
    u64 h0a = pack2(g[0][0], g[1][0]), h0b = pack2(g[2][0], g[3][0]);
    u64 h1a = pack2(g[0][1], g[1][1]), h1b = pack2(g[2][1], g[3][1]);
    u64 h2a = pack2(g[0][2], g[1][2]), h2b = pack2(g[2][2], g[3][2]);
    u64 h3a = pack2(g[0][3], g[1][3]), h3b = pack2(g[2][3], g[3][3]);
    u64 h4a = pack2(g[0][4], g[1][4]), h4b = pack2(g[2][4], g[3][4]);
    u64 h5a = pack2(g[0][5], g[1][5]), h5b = pack2(g[2][5], g[3][5]);
    u64 h6a = pack2(g[0][6], g[1][6]), h6b = pack2(g[2][6], g[3][6]);

    // ---- fc2..fc19: 9 ping-pong double-layer blocks, unique weight regs ----
#pragma unroll 1
    for (int l = 0; l < 9; l++) {
        unsigned saddr = sbase + (unsigned)l * 1024u;
        asm(
            "{\n\t"
            ".reg .b64 wa0_<8>, wa1_<8>, wa2_<8>, wa3_<8>, wa4_<8>, wa5_<8>, wa6_<8>;\n\t"
            ".reg .b64 wb0_<8>, wb1_<8>, wb2_<8>, wb3_<8>, wb4_<8>, wb5_<8>, wb6_<8>;\n\t"
            ".reg .b64 nA<7>, nB<7>, pA<7>, pB<7>, gA<7>, gB<7>;\n\t"
            ".reg .f32 ea<14>, ma<14>, eb<14>, mb<14>;\n\t"
            ".reg .f32 ua<14>, va<14>, ub<14>, vb<14>;\n\t"
            // ---- layer A: state -> gA/gB ----
            STEP(  "0", "16", "32", "48", "wa0_", INA, INB, "nA0","nB0","gA0","gB0",
                 "ea0","ea1","ma0","ma1","eb0","eb1","mb0","mb1")
            STEP( "64", "80", "96","112", "wa1_", INA, INB, "nA1","nB1","gA1","gB1",
                 "ea2","ea3","ma2","ma3","eb2","eb3","mb2","mb3")
            STEP("128","144","160","176", "wa2_", INA, INB, "nA2","nB2","gA2","gB2",
                 "ea4","ea5","ma4","ma5","eb4","eb5","mb4","mb5")
            STEP("192","208","224","240", "wa3_", INA, INB, "nA3","nB3","gA3","gB3",
                 "ea6","ea7","ma6","ma7","eb6","eb7","mb6","mb7")
            STEP("256","272","288","304", "wa4_", INA, INB, "nA4","nB4","gA4","gB4",
                 "ea8","ea9","ma8","ma9","eb8","eb9","mb8","mb9")
            STEP("320","336","352","368", "wa5_", INA, INB, "nA5","nB5","gA5","gB5",
                 "ea10","ea11","ma10","ma11","eb10","eb11","mb10","mb11")
            STEP("384","400","416","432", "wa6_", INA, INB, "nA6","nB6","gA6","gB6",
                 "ea12","ea13","ma12","ma13","eb12","eb13","mb12","mb13")
            // ---- layer B: gA/gB -> state ----
            STEP("512","528","544","560", "wb0_", GAS, GBS, "pA0","pB0","%0","%7",
                 "ua0","ua1","va0","va1","ub0","ub1","vb0","vb1")
            STEP("576","592","608","624", "wb1_", GAS, GBS, "pA1","pB1","%1","%8",
                 "ua2","ua3","va2","va3","ub2","ub3","vb2","vb3")
            STEP("640","656","672","688", "wb2_", GAS, GBS, "pA2","pB2","%2","%9",
                 "ua4","ua5","va4","va5","ub4","ub5","vb4","vb5")
            STEP("704","720","736","752", "wb3_", GAS, GBS, "pA3","pB3","%3","%10",
                 "ua6","ua7","va6","va7","ub6","ub7","vb6","vb7")
            STEP("768","784","800","816", "wb4_", GAS, GBS, "pA4","pB4","%4","%11",
                 "ua8","ua9","va8","va9","ub8","ub9","vb8","vb9")
            STEP("832","848","864","880", "wb5_", GAS, GBS, "pA5","pB5","%5","%12",
                 "ua10","ua11","va10","va11","ub10","ub11","vb10","vb11")
            STEP("896","912","928","944", "wb6_", GAS, GBS, "pA6","pB6","%6","%13",
                 "ua12","ua13","va12","va13","ub12","ub13","vb12","vb13")
            "}"
            : "+l"(h0a), "+l"(h1a), "+l"(h2a), "+l"(h3a),
              "+l"(h4a), "+l"(h5a), "+l"(h6a),
              "+l"(h0b), "+l"(h1b), "+l"(h2b), "+l"(h3b),
              "+l"(h4b), "+l"(h5b), "+l"(h6b)
            : "r"(saddr));
    }

    // ---- fc20 (layer 19): single block. WAR-safe: ELU outputs to fresh
    //      oA/oB regs; state updated by movs at the END. ----
    {
        unsigned saddr = sbase + 9216u;   // 18 * 512
        asm(
            "{\n\t"
            ".reg .b64 wc0_<8>, wc1_<8>, wc2_<8>, wc3_<8>, wc4_<8>, wc5_<8>, wc6_<8>;\n\t"
            ".reg .b64 nA<7>, nB<7>, oA<7>, oB<7>;\n\t"
            ".reg .f32 ea<14>, ma<14>, eb<14>, mb<14>;\n\t"
            STEP(  "0", "16", "32", "48", "wc0_", INA, INB, "nA0","nB0","oA0","oB0",
                 "ea0","ea1","ma0","ma1","eb0","eb1","mb0","mb1")
            STEP( "64", "80", "96","112", "wc1_", INA, INB, "nA1","nB1","oA1","oB1",
                 "ea2","ea3","ma2","ma3","eb2","eb3","mb2","mb3")
            STEP("128","144","160","176", "wc2_", INA, INB, "nA2","nB2","oA2","oB2",
                 "ea4","ea5","ma4","ma5","eb4","eb5","mb4","mb5")
            STEP("192","208","224","240", "wc3_", INA, INB, "nA3","nB3","oA3","oB3",
                 "ea6","ea7","ma6","ma7","eb6","eb7","mb6","mb7")
            STEP("256","272","288","304", "wc4_", INA, INB, "nA4","nB4","oA4","oB4",
                 "ea8","ea9","ma8","ma9","eb8","eb9","mb8","mb9")
            STEP("320","336","352","368", "wc5_", INA, INB, "nA5","nB5","oA5","oB5",
                 "ea10","ea11","ma10","ma11","eb10","eb11","mb10","mb11")
            STEP("384","400","416","432", "wc6_", INA, INB, "nA6","nB6","oA6","oB6",
                 "ea12","ea13","ma12","ma13","eb12","eb13","mb12","mb13")
            "mov.b64 %0, oA0;\n\t"  "mov.b64 %7,  oB0;\n\t"
            "mov.b64 %1, oA1;\n\t"  "mov.b64 %8,  oB1;\n\t"
            "mov.b64 %2, oA2;\n\t"  "mov.b64 %9,  oB2;\n\t"
            "mov.b64 %3, oA3;\n\t"  "mov.b64 %10, oB3;\n\t"
            "mov.b64 %4, oA4;\n\t"  "mov.b64 %11, oB4;\n\t"
            "mov.b64 %5, oA5;\n\t"  "mov.b64 %12, oB5;\n\t"
            "mov.b64 %6, oA6;\n\t"  "mov.b64 %13, oB6;\n\t"
            "}"
            : "+l"(h0a), "+l"(h1a), "+l"(h2a), "+l"(h3a),
              "+l"(h4a), "+l"(h5a), "+l"(h6a),
              "+l"(h0b), "+l"(h1b), "+l"(h2b), "+l"(h3b),
              "+l"(h4b), "+l"(h5b), "+l"(h6b)
            : "r"(saddr));
    }

    // ---- fc21: logits = (ln2*Wo)*G + bias-fold ----
    u64 lpa[2], lpb[2];
#pragma unroll
    for (int r = 0; r < 2; r++) {
        const ulonglong2* p = reinterpret_cast<const ulonglong2*>(&sFcO[r * 8]);
        ulonglong2 q0 = p[0], q1 = p[1], q2 = p[2], q3 = p[3];
        u64 acca = q3.y, accb = q3.y;
        acca = fma2(q0.x, h0a, acca);  accb = fma2(q0.x, h0b, accb);
        acca = fma2(q0.y, h1a, acca);  accb = fma2(q0.y, h1b, accb);
        acca = fma2(q1.x, h2a, acca);  accb = fma2(q1.x, h2b, accb);
        acca = fma2(q1.y, h3a, acca);  accb = fma2(q1.y, h3b, accb);
        acca = fma2(q2.x, h4a, acca);  accb = fma2(q2.x, h4b, accb);
        acca = fma2(q2.y, h5a, acca);  accb = fma2(q2.y, h5b, accb);
        acca = fma2(q3.x, h6a, acca);  accb = fma2(q3.x, h6b, accb);
        lpa[r] = acca;  lpb[r] = accb;
    }

    float a0lo, a0hi, a1lo, a1hi, b0lo, b0hi, b1lo, b1hi;
    unpack2(lpa[0], a0lo, a0hi);  unpack2(lpa[1], a1lo, a1hi);
    unpack2(lpb[0], b0lo, b0hi);  unpack2(lpb[1], b1lo, b1hi);

    auto lsm = [](float l0, float l1, float& o0, float& o1) {
        float m   = fmaxf(l0, l1);
        float s   = ex2f((l0 - m) * 1.44269504088896340736f)
                  + ex2f((l1 - m) * 1.44269504088896340736f);
        float lse = m + __logf(s);
        o0 = l0 - lse;  o1 = l1 - lse;
    };

    float4 oa, ob;
    lsm(a0lo, a1lo, oa.x, oa.y);
    lsm(a0hi, a1hi, oa.z, oa.w);
    lsm(b0lo, b1lo, ob.x, ob.y);
    lsm(b0hi, b1hi, ob.z, ob.w);

    reinterpret_cast<float4*>(out)[2 * q + 0] = oa;
    reinterpret_cast<float4*>(out)[2 * q + 1] = ob;
}

extern "C" void kernel_launch(void* const* d_in, const int* in_sizes, int n_in,
                              void* d_out, int out_size)
{
    const float* x  = (const float*)d_in[0];
    const float* W1 = (const float*)d_in[1];
    const float* b1 = (const float*)d_in[2];
    const float* Wm = (const float*)d_in[3];
    const float* bm = (const float*)d_in[4];
    const float* Wo = (const float*)d_in[5];
    const float* bo = (const float*)d_in[6];
    float* out = (float*)d_out;

    int nQuads = in_sizes[0] / 8;   // x is [B,2]; 4 rows per thread
    int grid = (nQuads + THREADS - 1) / THREADS;
    net0_kernel<<<grid, THREADS>>>(x, W1, b1, Wm, bm, Wo, bo, out, nQuads);
}

// round 17
// speedup vs baseline: 1.1817x; 1.1817x over previous
#include <cuda_runtime.h>

// Net0: x[B,2] -> fc1(2,7)+ELU -> 19x fc(7,7)+ELU -> fc(7,2) -> log_softmax.
// R17: weights live in __constant__ memory (preprocessed by a prep kernel and
// copied via cudaMemcpyToSymbolAsync D2D). Uniform constant loads lower to
// LDCU -> uniform registers -> FFMA with UR operand (2 RF reads) which, like
// the imm form, can issue at rt1 instead of rt2 -- attacking the measured
// 126-fma-instr x rt2 = 252 cyc/warp-layer floor that has pinned R3..R16.
// Algebra (validated R9-R16): state t = z*log2e; G = log2e*(elu(z)+1)
//   = log2e*exp2(min(t,0)) + max(t,0); mid weights RAW (ln2*log2e=1);
//   bias' = (b - rowsum(W))*log2e; fc21: logits = (ln2*Wo)*G + (bo - rowsum(Wo)).

constexpr int H       = 7;
constexpr int NMID    = 19;
constexpr int THREADS = 256;

typedef unsigned long long u64;

// ---- constant-space weight images (filled at runtime via MemcpyToSymbol) ----
__constant__ float      cFc1[H * 3];          // per i: w0,w1,b   (x log2e)
__constant__ ulonglong2 cMid2[NMID * 32];     // per layer: i*4 + {w01,w23,w45,w6b'} (dup pairs)
__constant__ ulonglong2 cFcO2[2 * 4];         // per r: w01,w23,w45,w6b'' (ln2*Wo, bias-fold)

// ---- staging buffers (device globals; prep kernel writes, memcpy to const) ----
__device__ float      gFc1[H * 3];
__device__ ulonglong2 gMid2[NMID * 32];
__device__ ulonglong2 gFcO2[2 * 4];

__device__ __forceinline__ u64 dupf(float v) {
    unsigned u = __float_as_uint(v);
    return ((u64)u << 32) | (u64)u;
}

__global__ void prep_kernel(const float* __restrict__ W1, const float* __restrict__ b1,
                            const float* __restrict__ Wm, const float* __restrict__ bm,
                            const float* __restrict__ Wo, const float* __restrict__ bo)
{
    const float LOG2E = 1.44269504088896340736f;
    const float LN2   = 0.69314718055994530942f;
    int tid = blockIdx.x * blockDim.x + threadIdx.x;

    if (tid < H) {
        gFc1[tid * 3 + 0] = W1[tid * 2 + 0] * LOG2E;
        gFc1[tid * 3 + 1] = W1[tid * 2 + 1] * LOG2E;
        gFc1[tid * 3 + 2] = b1[tid] * LOG2E;
    }
    if (tid < NMID * H) {                      // one thread per (layer, neuron i)
        int l = tid / H, i = tid - l * H;
        float w[H]; float s = 0.0f;
#pragma unroll
        for (int j = 0; j < H; j++) { w[j] = Wm[(l * H + i) * H + j]; s += w[j]; }
        float bp = (bm[l * H + i] - s) * LOG2E;
        gMid2[l * 32 + i * 4 + 0] = make_ulonglong2(dupf(w[0]), dupf(w[1]));
        gMid2[l * 32 + i * 4 + 1] = make_ulonglong2(dupf(w[2]), dupf(w[3]));
        gMid2[l * 32 + i * 4 + 2] = make_ulonglong2(dupf(w[4]), dupf(w[5]));
        gMid2[l * 32 + i * 4 + 3] = make_ulonglong2(dupf(w[6]), dupf(bp));
    }
    if (tid < 2) {
        int r = tid; float w[H]; float s = 0.0f;
#pragma unroll
        for (int j = 0; j < H; j++) { w[j] = Wo[r * H + j]; s += w[j]; }
        float bf = bo[r] - s;
        gFcO2[r * 4 + 0] = make_ulonglong2(dupf(w[0] * LN2), dupf(w[1] * LN2));
        gFcO2[r * 4 + 1] = make_ulonglong2(dupf(w[2] * LN2), dupf(w[3] * LN2));
        gFcO2[r * 4 + 2] = make_ulonglong2(dupf(w[4] * LN2), dupf(w[5] * LN2));
        gFcO2[r * 4 + 3] = make_ulonglong2(dupf(w[6] * LN2), dupf(bf));
    }
}

// ---- math helpers ----
__device__ __forceinline__ u64 pack2(float lo, float hi) {
    u64 r; asm("mov.b64 %0, {%1, %2};" : "=l"(r) : "f"(lo), "f"(hi)); return r;
}
__device__ __forceinline__ void unpack2(u64 v, float& lo, float& hi) {
    asm("mov.b64 {%0, %1}, %2;" : "=f"(lo), "=f"(hi) : "l"(v));
}
__device__ __forceinline__ u64 fma2(u64 a, u64 b, u64 c) {
    u64 d; asm("fma.rn.f32x2 %0, %1, %2, %3;" : "=l"(d) : "l"(a), "l"(b), "l"(c));
    return d;
}
__device__ __forceinline__ float ex2f(float x) {
    float r; asm("ex2.approx.f32 %0, %1;" : "=f"(r) : "f"(x)); return r;
}
__device__ __forceinline__ float eluG1(float t) {   // scalar, fc1 only
    return fmaf(1.44269504088896340736f, ex2f(fminf(t, 0.0f)), fmaxf(t, 0.0f));
}
// G = log2e*exp2(min(t,0)) + max(t,0); imm-form FFMA (rt1).
__device__ __forceinline__ u64 eluG(u64 t) {
    u64 g;
    asm("{\n\t"
        ".reg .f32 tl, th, el, eh;\n\t"
        "mov.b64 {tl, th}, %1;\n\t"
        "min.f32 el, tl, 0f00000000;\n\t"
        "min.f32 eh, th, 0f00000000;\n\t"
        "ex2.approx.f32 el, el;\n\t"
        "ex2.approx.f32 eh, eh;\n\t"
        "max.f32 tl, tl, 0f00000000;\n\t"
        "max.f32 th, th, 0f00000000;\n\t"
        "fma.rn.f32 tl, el, 0f3FB8AA3B, tl;\n\t"
        "fma.rn.f32 th, eh, 0f3FB8AA3B, th;\n\t"
        "mov.b64 %0, {tl, th};\n\t"
        "}" : "=l"(g) : "l"(t));
    return g;
}

__global__ void __launch_bounds__(THREADS, 3)
net0_kernel(const float* __restrict__ x, float* __restrict__ out, int nQuads)
{
    int q = blockIdx.x * THREADS + threadIdx.x;   // 4 rows per thread
    if (q >= nQuads) return;

    float4 xa = reinterpret_cast<const float4*>(x)[2 * q + 0];  // rows 4q,4q+1
    float4 xb = reinterpret_cast<const float4*>(x)[2 * q + 1];  // rows 4q+2,4q+3

    // ---- fc1 (t-scale) + ELU(G), scalar; weights from constant bank ----
    float g[4][H];
#pragma unroll
    for (int i = 0; i < H; i++) {
        float w0 = cFc1[i * 3 + 0];
        float w1 = cFc1[i * 3 + 1];
        float bb = cFc1[i * 3 + 2];
        g[0][i] = eluG1(fmaf(w0, xa.x, fmaf(w1, xa.y, bb)));
        g[1][i] = eluG1(fmaf(w0, xa.z, fmaf(w1, xa.w, bb)));
        g[2][i] = eluG1(fmaf(w0, xb.x, fmaf(w1, xb.y, bb)));
        g[3][i] = eluG1(fmaf(w0, xb.z, fmaf(w1, xb.w, bb)));
    }
    u64 ha[H], hb[H];
#pragma unroll
    for (int i = 0; i < H; i++) {
        ha[i] = pack2(g[0][i], g[1][i]);
        hb[i] = pack2(g[2][i], g[3][i]);
    }

    // ---- fc2..fc20: weights read uniformly from __constant__ (LDCU/UR path) ----
#pragma unroll 1
    for (int l = 0; l < NMID; l++) {
        const ulonglong2* base = &cMid2[l * 32];
        u64 na[H], nb[H];
#pragma unroll
        for (int i = 0; i < H; i++) {
            ulonglong2 q0 = base[i * 4 + 0];   // w0,w1 (dup)
            ulonglong2 q1 = base[i * 4 + 1];   // w2,w3
            ulonglong2 q2 = base[i * 4 + 2];   // w4,w5
            ulonglong2 q3 = base[i * 4 + 3];   // w6,bias'
            u64 acca = q3.y, accb = q3.y;
            acca = fma2(q0.x, ha[0], acca);  accb = fma2(q0.x, hb[0], accb);
            acca = fma2(q0.y, ha[1], acca);  accb = fma2(q0.y, hb[1], accb);
            acca = fma2(q1.x, ha[2], acca);  accb = fma2(q1.x, hb[2], accb);
            acca = fma2(q1.y, ha[3], acca);  accb = fma2(q1.y, hb[3], accb);
            acca = fma2(q2.x, ha[4], acca);  accb = fma2(q2.x, hb[4], accb);
            acca = fma2(q2.y, ha[5], acca);  accb = fma2(q2.y, hb[5], accb);
            acca = fma2(q3.x, ha[6], acca);  accb = fma2(q3.x, hb[6], accb);
            na[i] = acca;  nb[i] = accb;
        }
#pragma unroll
        for (int i = 0; i < H; i++) {
            ha[i] = eluG(na[i]);
            hb[i] = eluG(nb[i]);
        }
    }

    // ---- fc21: logits = (ln2*Wo)*G + bias-fold ----
    u64 lpa[2], lpb[2];
#pragma unroll
    for (int r = 0; r < 2; r++) {
        ulonglong2 q0 = cFcO2[r * 4 + 0], q1 = cFcO2[r * 4 + 1];
        ulonglong2 q2 = cFcO2[r * 4 + 2], q3 = cFcO2[r * 4 + 3];
        u64 acca = q3.y, accb = q3.y;
        acca = fma2(q0.x, ha[0], acca);  accb = fma2(q0.x, hb[0], accb);
        acca = fma2(q0.y, ha[1], acca);  accb = fma2(q0.y, hb[1], accb);
        acca = fma2(q1.x, ha[2], acca);  accb = fma2(q1.x, hb[2], accb);
        acca = fma2(q1.y, ha[3], acca);  accb = fma2(q1.y, hb[3], accb);
        acca = fma2(q2.x, ha[4], acca);  accb = fma2(q2.x, hb[4], accb);
        acca = fma2(q2.y, ha[5], acca);  accb = fma2(q2.y, hb[5], accb);
        acca = fma2(q3.x, ha[6], acca);  accb = fma2(q3.x, hb[6], accb);
        lpa[r] = acca;  lpb[r] = accb;
    }

    float a0lo, a0hi, a1lo, a1hi, b0lo, b0hi, b1lo, b1hi;
    unpack2(lpa[0], a0lo, a0hi);  unpack2(lpa[1], a1lo, a1hi);
    unpack2(lpb[0], b0lo, b0hi);  unpack2(lpb[1], b1lo, b1hi);

    auto lsm = [](float l0, float l1, float& o0, float& o1) {
        float m   = fmaxf(l0, l1);
        float s   = ex2f((l0 - m) * 1.44269504088896340736f)
                  + ex2f((l1 - m) * 1.44269504088896340736f);
        float lse = m + __logf(s);
        o0 = l0 - lse;  o1 = l1 - lse;
    };

    float4 oa, ob;
    lsm(a0lo, a1lo, oa.x, oa.y);   // row 4q
    lsm(a0hi, a1hi, oa.z, oa.w);   // row 4q+1
    lsm(b0lo, b1lo, ob.x, ob.y);   // row 4q+2
    lsm(b0hi, b1hi, ob.z, ob.w);   // row 4q+3

    reinterpret_cast<float4*>(out)[2 * q + 0] = oa;
    reinterpret_cast<float4*>(out)[2 * q + 1] = ob;
}

extern "C" void kernel_launch(void* const* d_in, const int* in_sizes, int n_in,
                              void* d_out, int out_size)
{
    const float* x  = (const float*)d_in[0];
    const float* W1 = (const float*)d_in[1];
    const float* b1 = (const float*)d_in[2];
    const float* Wm = (const float*)d_in[3];
    const float* bm = (const float*)d_in[4];
    const float* Wo = (const float*)d_in[5];
    const float* bo = (const float*)d_in[6];
    float* out = (float*)d_out;

    // 1) preprocess weights into device globals (1 block is enough: NMID*H=133)
    prep_kernel<<<1, 256>>>(W1, b1, Wm, bm, Wo, bo);

    // 2) async D2D copies global -> constant bank (graph-capturable, no alloc)
    void* p;
    cudaGetSymbolAddress(&p, gFc1);
    cudaMemcpyToSymbolAsync(cFc1,  p, sizeof(float) * H * 3,        0,
                            cudaMemcpyDeviceToDevice, 0);
    cudaGetSymbolAddress(&p, gMid2);
    cudaMemcpyToSymbolAsync(cMid2, p, sizeof(ulonglong2) * NMID * 32, 0,
                            cudaMemcpyDeviceToDevice, 0);
    cudaGetSymbolAddress(&p, gFcO2);
    cudaMemcpyToSymbolAsync(cFcO2, p, sizeof(ulonglong2) * 2 * 4,   0,
                            cudaMemcpyDeviceToDevice, 0);

    // 3) main kernel
    int nQuads = in_sizes[0] / 8;   // x is [B,2]; 4 rows per thread
    int grid = (nQuads + THREADS - 1) / THREADS;
    net0_kernel<<<grid, THREADS>>>(x, out, nQuads);
}